// round 14
// baseline (speedup 1.0000x reference)
#include <cuda_runtime.h>
#include <cuda_fp16.h>
#include <cstdint>

// Problem constants
#define TOKENS   4096
#define IN_F     4096
#define OUT_F    11008
#define QGROUPS  64
#define KWORDS   (IN_F / 8)       // 512 packed int32 per output row

// GEMM tiling: 64x128x64, 2-stage, 4 CTAs/SM (16 warps/SM).
#define BM       64
#define BN       128
#define BK       64               // fp16 elements per stage along K (128B rows)
#define NKIT     (IN_F / BK)      // 64
#define NTHREADS 128              // 4 warps, 2x2 grid of 32x64 warp tiles
#define A_STAGE_BYTES (BM * BK * 2)               // 8192
#define B_STAGE_BYTES (BN * BK * 2)               // 16384
#define STAGE_BYTES   (A_STAGE_BYTES + B_STAGE_BYTES)  // 24576
#define SMEM_TOTAL    (2 * STAGE_BYTES)           // 49152 (4 CTAs -> 192KB/SM)

#define NMT      (TOKENS / BM)    // 64 M tiles
#define NNT      (OUT_F / BN)     // 86 N tiles

// Scratch (device globals: allocation-free rule)
__device__ __half g_Bh[(size_t)OUT_F * IN_F];   // dequantized fp16 weights
__device__ __half g_Xh[(size_t)TOKENS * IN_F];  // fp16 activations

// ---------------------------------------------------------------------------
// Helpers
// ---------------------------------------------------------------------------
__device__ __forceinline__ uint32_t smem_u32(const void* p) {
    uint32_t a;
    asm("{ .reg .u64 t; cvta.to.shared.u64 t, %1; cvt.u32.u64 %0, t; }"
        : "=r"(a) : "l"(p));
    return a;
}

__device__ __forceinline__ void ldsm_x4(uint32_t addr, uint32_t* r) {
    asm volatile("ldmatrix.sync.aligned.m8n8.x4.shared.b16 {%0,%1,%2,%3}, [%4];"
                 : "=r"(r[0]), "=r"(r[1]), "=r"(r[2]), "=r"(r[3]) : "r"(addr));
}

__device__ __forceinline__ void mma16816(float* c, const uint32_t* a,
                                         uint32_t b0, uint32_t b1) {
    asm volatile(
        "mma.sync.aligned.m16n8k16.row.col.f32.f16.f16.f32 "
        "{%0,%1,%2,%3}, {%4,%5,%6,%7}, {%8,%9}, {%0,%1,%2,%3};"
        : "+f"(c[0]), "+f"(c[1]), "+f"(c[2]), "+f"(c[3])
        : "r"(a[0]), "r"(a[1]), "r"(a[2]), "r"(a[3]), "r"(b0), "r"(b1));
}

// ---------------------------------------------------------------------------
// Fused pre-kernel: blocks [0, NCONV_BLKS) convert x -> fp16; the rest
// dequantize int4 weights -> fp16. Independent jobs, run concurrently.
// fp16 mantissa step = 2^-11 -> output rel_err ~2.7e-4 < 1e-3.
// ---------------------------------------------------------------------------
#define NCONV_ELEMS (TOKENS * IN_F / 8)           // uint4 stores: 2097152
#define NCONV_BLKS  ((NCONV_ELEMS + 255) / 256)   // 8192
#define NDEQ_ELEMS  (OUT_F * KWORDS)              // 5636096
#define NDEQ_BLKS   ((NDEQ_ELEMS + 255) / 256)    // 22016

__global__ void prep_kernel(const float4* __restrict__ x,
                            const uint32_t* __restrict__ qw,
                            const uint32_t* __restrict__ qz,
                            const float* __restrict__ sc) {
    if (blockIdx.x < NCONV_BLKS) {
        int i = blockIdx.x * 256 + threadIdx.x;
        if (i >= NCONV_ELEMS) return;
        float4 a = x[2 * i];
        float4 b = x[2 * i + 1];
        __half2 h0 = __floats2half2_rn(a.x, a.y);
        __half2 h1 = __floats2half2_rn(a.z, a.w);
        __half2 h2 = __floats2half2_rn(b.x, b.y);
        __half2 h3 = __floats2half2_rn(b.z, b.w);
        uint4 o;
        o.x = *reinterpret_cast<uint32_t*>(&h0);
        o.y = *reinterpret_cast<uint32_t*>(&h1);
        o.z = *reinterpret_cast<uint32_t*>(&h2);
        o.w = *reinterpret_cast<uint32_t*>(&h3);
        reinterpret_cast<uint4*>(g_Xh)[i] = o;
    } else {
        int idx = (blockIdx.x - NCONV_BLKS) * 256 + threadIdx.x;
        if (idx >= NDEQ_ELEMS) return;
        int o  = idx >> 9;              // / 512
        int kw = idx & (KWORDS - 1);
        int g  = kw >> 3;               // group (8 words per 64-elem group)
        float s = sc[o * QGROUPS + g];
        uint32_t zw = qz[o * (QGROUPS / 8) + (g >> 3)];
        float zp = (float)((zw >> ((g & 7) * 4)) & 0xF);
        float c  = -s * zp;             // w = s*v + c; |w| <= 0.15, fp16-safe
        uint32_t w = qw[idx];
        __half2 h0 = __floats2half2_rn(fmaf(s, (float)((w      ) & 0xF), c),
                                       fmaf(s, (float)((w >>  4) & 0xF), c));
        __half2 h1 = __floats2half2_rn(fmaf(s, (float)((w >>  8) & 0xF), c),
                                       fmaf(s, (float)((w >> 12) & 0xF), c));
        __half2 h2 = __floats2half2_rn(fmaf(s, (float)((w >> 16) & 0xF), c),
                                       fmaf(s, (float)((w >> 20) & 0xF), c));
        __half2 h3 = __floats2half2_rn(fmaf(s, (float)((w >> 24) & 0xF), c),
                                       fmaf(s, (float)((w >> 28) & 0xF), c));
        uint4 o4;
        o4.x = *reinterpret_cast<uint32_t*>(&h0);
        o4.y = *reinterpret_cast<uint32_t*>(&h1);
        o4.z = *reinterpret_cast<uint32_t*>(&h2);
        o4.w = *reinterpret_cast<uint32_t*>(&h3);
        reinterpret_cast<uint4*>(g_Bh + (size_t)o * IN_F)[kw] = o4;
    }
}

// ---------------------------------------------------------------------------
// Main GEMM: mma.sync.m16n8k16 fp16 -> f32, CTA 64x128x64, 2-stage cp.async,
// 4 CTAs per SM (16 warps/SM). The 12 cp.async of stage kt+1 are SPREAD
// across the 4 k16 compute steps (A at step 0, B halves at steps 1,2) so LSU
// issue interleaves with tensor work instead of bursting at the barrier exit.
// 4 warps in 2(M) x 2(N) grid; warp tile 32x64.
// Smem: K-major 128B rows, SW128 swizzle -> conflict-free ldmatrix.
// ---------------------------------------------------------------------------
__global__ void __launch_bounds__(NTHREADS, 4)
gemm_f16_kernel(const float* __restrict__ bias, float* __restrict__ out) {
    extern __shared__ __align__(1024) char smem[];
    const uint32_t sbase = smem_u32(smem);
    const int tid  = threadIdx.x;
    const int wid  = tid >> 5;
    const int lane = tid & 31;
    const int wm   = wid & 1;        // warp M coord (2)
    const int wn   = wid >> 1;       // warp N coord (2)

    // M-fastest CTA order: concurrent CTAs share B bands; A stays L2-resident.
    const int mt = blockIdx.x & (NMT - 1);  // 64 M tiles
    const int nt = blockIdx.x >> 6;         // 86 N tiles
    const int m0 = mt * BM;
    const int n0 = nt * BN;

    const __half* Abase = g_Xh + (size_t)m0 * IN_F;
    const __half* Bbase = g_Bh + (size_t)n0 * IN_F;

    // Per-thread load coordinates (fixed): 16B chunks, rows strided by 16.
    const int lr = tid >> 3;          // base row 0..15
    const int lc = tid & 7;           // 16B chunk 0..7

    auto load_A = [&](int s, int kl) {
        const uint32_t abuf = sbase + s * STAGE_BYTES;
        const __half* Ag = Abase + kl * BK;
        #pragma unroll
        for (int j = 0; j < 4; j++) {
            int r = lr + j * 16;                  // A row 0..63
            uint32_t off = (uint32_t)(r * 128 + lc * 16);
            uint32_t sw  = off ^ ((off >> 3) & 0x70);
            asm volatile("cp.async.cg.shared.global [%0], [%1], 16;"
                         :: "r"(abuf + sw), "l"(Ag + (size_t)r * IN_F + lc * 8)
                         : "memory");
        }
    };
    auto load_B = [&](int s, int kl, int h) {
        const uint32_t bbuf = sbase + s * STAGE_BYTES + A_STAGE_BYTES;
        const __half* Bg = Bbase + kl * BK;
        #pragma unroll
        for (int j = 0; j < 4; j++) {
            int r = h * 64 + lr + j * 16;         // B row (half h)
            uint32_t off = (uint32_t)(r * 128 + lc * 16);
            uint32_t sw  = off ^ ((off >> 3) & 0x70);
            asm volatile("cp.async.cg.shared.global [%0], [%1], 16;"
                         :: "r"(bbuf + sw), "l"(Bg + (size_t)r * IN_F + lc * 8)
                         : "memory");
        }
    };

    // Prologue: fill stage 0
    load_A(0, 0);
    load_B(0, 0, 0);
    load_B(0, 0, 1);
    asm volatile("cp.async.commit_group;" ::: "memory");

    float acc[2][8][4];
    #pragma unroll
    for (int mi = 0; mi < 2; mi++)
        #pragma unroll
        for (int nf = 0; nf < 8; nf++)
            #pragma unroll
            for (int e = 0; e < 4; e++) acc[mi][nf][e] = 0.0f;

    const int lrow   = lane & 15;    // ldmatrix source row within 16
    const int lchunk = lane >> 4;    // 0: k0-7 chunk, 1: k8-15 chunk

    for (int kt = 0; kt < NKIT; kt++) {
        asm volatile("cp.async.wait_group %0;" :: "n"(0) : "memory");
        __syncthreads();

        const int s = kt & 1;
        const uint32_t abuf = sbase + s * STAGE_BYTES;
        const uint32_t bbuf = abuf + A_STAGE_BYTES;
        const int kl = kt + 1;
        const int sn = kl & 1;
        const bool more = (kl < NKIT);

        #pragma unroll
        for (int k16 = 0; k16 < BK / 16; k16++) {
            uint32_t af[2][4], bf[4][4];
            const int chunk = k16 * 2 + lchunk;
            #pragma unroll
            for (int mi = 0; mi < 2; mi++) {
                int row = wm * 32 + mi * 16 + lrow;
                uint32_t off = (uint32_t)(row * 128 + chunk * 16);
                ldsm_x4(abuf + (off ^ ((off >> 3) & 0x70)), af[mi]);
            }
            #pragma unroll
            for (int nj = 0; nj < 4; nj++) {
                int row = wn * 64 + nj * 16 + lrow;
                uint32_t off = (uint32_t)(row * 128 + chunk * 16);
                ldsm_x4(bbuf + (off ^ ((off >> 3) & 0x70)), bf[nj]);
            }
            // Spread next-stage loads across the compute steps (LSU interleave)
            if (more) {
                if (k16 == 0)      load_A(sn, kl);
                else if (k16 == 1) load_B(sn, kl, 0);
                else if (k16 == 2) load_B(sn, kl, 1);
            }
            #pragma unroll
            for (int mi = 0; mi < 2; mi++)
                #pragma unroll
                for (int nj = 0; nj < 4; nj++) {
                    mma16816(acc[mi][2 * nj],     af[mi], bf[nj][0], bf[nj][2]);
                    mma16816(acc[mi][2 * nj + 1], af[mi], bf[nj][1], bf[nj][3]);
                }
        }
        asm volatile("cp.async.commit_group;" ::: "memory");
    }

    // Epilogue: fragment layout c0,c1 -> (row=q, col=2c..2c+1), c2,c3 -> row+8.
    const int qrow = lane >> 2;          // 0..7
    const int qcol = (lane & 3) * 2;
    #pragma unroll
    for (int mi = 0; mi < 2; mi++) {
        int gr = m0 + wm * 32 + mi * 16 + qrow;
        float* p0 = out + (size_t)gr * OUT_F;
        float* p1 = p0 + 8 * OUT_F;
        #pragma unroll
        for (int nf = 0; nf < 8; nf++) {
            int col = n0 + wn * 64 + nf * 8 + qcol;
            float bx = __ldg(bias + col);
            float by = __ldg(bias + col + 1);
            float2 v0, v1;
            v0.x = acc[mi][nf][0] + bx;
            v0.y = acc[mi][nf][1] + by;
            v1.x = acc[mi][nf][2] + bx;
            v1.y = acc[mi][nf][3] + by;
            *reinterpret_cast<float2*>(p0 + col) = v0;
            *reinterpret_cast<float2*>(p1 + col) = v1;
        }
    }
}

// ---------------------------------------------------------------------------
extern "C" void kernel_launch(void* const* d_in, const int* in_sizes, int n_in,
                              void* d_out, int out_size) {
    const float*    x    = (const float*)   d_in[0];
    const uint32_t* qw   = (const uint32_t*)d_in[1];
    const uint32_t* qz   = (const uint32_t*)d_in[2];
    const float*    sc   = (const float*)   d_in[3];
    const float*    bias = (const float*)   d_in[4];
    float*          out  = (float*)d_out;

    // 1) fused: x -> fp16  ||  int4 dequant -> fp16 (concurrent)
    prep_kernel<<<NCONV_BLKS + NDEQ_BLKS, 256>>>((const float4*)x, qw, qz, sc);

    // 2) fp16 mma.sync GEMM, 4 CTAs/SM, interleaved cp.async issue
    cudaFuncSetAttribute(gemm_f16_kernel,
                         cudaFuncAttributeMaxDynamicSharedMemorySize, SMEM_TOTAL);
    dim3 grid(NMT * NNT);  // 64 * 86 = 5504, M-fastest
    gemm_f16_kernel<<<grid, NTHREADS, SMEM_TOTAL>>>(bias, out);
}

// round 15
// speedup vs baseline: 1.0864x; 1.0864x over previous
#include <cuda_runtime.h>
#include <cuda_fp16.h>
#include <cstdint>

// Problem constants
#define TOKENS   4096
#define IN_F     4096
#define OUT_F    11008
#define QGROUPS  64
#define KWORDS   (IN_F / 8)       // 512 packed int32 per output row

// GEMM tiling: 64x128x64, 2-stage, 4 CTAs/SM (16 warps/SM). R13 schedule.
#define BM       64
#define BN       128
#define BK       64               // fp16 elements per stage along K (128B rows)
#define NKIT     (IN_F / BK)      // 64
#define NTHREADS 128              // 4 warps, 2x2 grid of 32x64 warp tiles
#define A_STAGE_BYTES (BM * BK * 2)               // 8192
#define B_STAGE_BYTES (BN * BK * 2)               // 16384
#define STAGE_BYTES   (A_STAGE_BYTES + B_STAGE_BYTES)  // 24576
#define SMEM_TOTAL    (2 * STAGE_BYTES)           // 49152 (4 CTAs -> 192KB/SM)

#define NMT      (TOKENS / BM)    // 64 M tiles
#define NNT      (OUT_F / BN)     // 86 N tiles

// Scratch (device globals: allocation-free rule)
__device__ __half g_Bh[(size_t)OUT_F * IN_F];   // dequantized fp16 weights
__device__ __half g_Xh[(size_t)TOKENS * IN_F];  // fp16 activations

// ---------------------------------------------------------------------------
// Helpers
// ---------------------------------------------------------------------------
__device__ __forceinline__ uint32_t smem_u32(const void* p) {
    uint32_t a;
    asm("{ .reg .u64 t; cvta.to.shared.u64 t, %1; cvt.u32.u64 %0, t; }"
        : "=r"(a) : "l"(p));
    return a;
}

__device__ __forceinline__ void ldsm_x4(uint32_t addr, uint32_t* r) {
    asm volatile("ldmatrix.sync.aligned.m8n8.x4.shared.b16 {%0,%1,%2,%3}, [%4];"
                 : "=r"(r[0]), "=r"(r[1]), "=r"(r[2]), "=r"(r[3]) : "r"(addr));
}

__device__ __forceinline__ void mma16816(float* c, const uint32_t* a,
                                         uint32_t b0, uint32_t b1) {
    asm volatile(
        "mma.sync.aligned.m16n8k16.row.col.f32.f16.f16.f32 "
        "{%0,%1,%2,%3}, {%4,%5,%6,%7}, {%8,%9}, {%0,%1,%2,%3};"
        : "+f"(c[0]), "+f"(c[1]), "+f"(c[2]), "+f"(c[3])
        : "r"(a[0]), "r"(a[1]), "r"(a[2]), "r"(a[3]), "r"(b0), "r"(b1));
}

// ---------------------------------------------------------------------------
// Fused pre-kernel: blocks [0, NCONV_BLKS) convert x -> fp16; the rest
// dequantize int4 weights -> fp16. Independent jobs, run concurrently.
// fp16 mantissa step = 2^-11 -> output rel_err ~2.7e-4 < 1e-3.
// ---------------------------------------------------------------------------
#define NCONV_ELEMS (TOKENS * IN_F / 8)           // uint4 stores: 2097152
#define NCONV_BLKS  ((NCONV_ELEMS + 255) / 256)   // 8192
#define NDEQ_ELEMS  (OUT_F * KWORDS)              // 5636096
#define NDEQ_BLKS   ((NDEQ_ELEMS + 255) / 256)    // 22016

__global__ void prep_kernel(const float4* __restrict__ x,
                            const uint32_t* __restrict__ qw,
                            const uint32_t* __restrict__ qz,
                            const float* __restrict__ sc) {
    if (blockIdx.x < NCONV_BLKS) {
        int i = blockIdx.x * 256 + threadIdx.x;
        if (i >= NCONV_ELEMS) return;
        float4 a = x[2 * i];
        float4 b = x[2 * i + 1];
        __half2 h0 = __floats2half2_rn(a.x, a.y);
        __half2 h1 = __floats2half2_rn(a.z, a.w);
        __half2 h2 = __floats2half2_rn(b.x, b.y);
        __half2 h3 = __floats2half2_rn(b.z, b.w);
        uint4 o;
        o.x = *reinterpret_cast<uint32_t*>(&h0);
        o.y = *reinterpret_cast<uint32_t*>(&h1);
        o.z = *reinterpret_cast<uint32_t*>(&h2);
        o.w = *reinterpret_cast<uint32_t*>(&h3);
        reinterpret_cast<uint4*>(g_Xh)[i] = o;
    } else {
        int idx = (blockIdx.x - NCONV_BLKS) * 256 + threadIdx.x;
        if (idx >= NDEQ_ELEMS) return;
        int o  = idx >> 9;              // / 512
        int kw = idx & (KWORDS - 1);
        int g  = kw >> 3;               // group (8 words per 64-elem group)
        float s = sc[o * QGROUPS + g];
        uint32_t zw = qz[o * (QGROUPS / 8) + (g >> 3)];
        float zp = (float)((zw >> ((g & 7) * 4)) & 0xF);
        float c  = -s * zp;             // w = s*v + c; |w| <= 0.15, fp16-safe
        uint32_t w = qw[idx];
        __half2 h0 = __floats2half2_rn(fmaf(s, (float)((w      ) & 0xF), c),
                                       fmaf(s, (float)((w >>  4) & 0xF), c));
        __half2 h1 = __floats2half2_rn(fmaf(s, (float)((w >>  8) & 0xF), c),
                                       fmaf(s, (float)((w >> 12) & 0xF), c));
        __half2 h2 = __floats2half2_rn(fmaf(s, (float)((w >> 16) & 0xF), c),
                                       fmaf(s, (float)((w >> 20) & 0xF), c));
        __half2 h3 = __floats2half2_rn(fmaf(s, (float)((w >> 24) & 0xF), c),
                                       fmaf(s, (float)((w >> 28) & 0xF), c));
        uint4 o4;
        o4.x = *reinterpret_cast<uint32_t*>(&h0);
        o4.y = *reinterpret_cast<uint32_t*>(&h1);
        o4.z = *reinterpret_cast<uint32_t*>(&h2);
        o4.w = *reinterpret_cast<uint32_t*>(&h3);
        reinterpret_cast<uint4*>(g_Bh + (size_t)o * IN_F)[kw] = o4;
    }
}

// ---------------------------------------------------------------------------
// Main GEMM: mma.sync.m16n8k16 fp16 -> f32, CTA 64x128x64, 2-stage cp.async,
// 4 CTAs per SM (16 warps/SM). R13 schedule (burst loads after barrier),
// with strength-reduced addressing: loop-carried global pointers with
// compile-time immediate row offsets, and precomputed swizzled smem store
// offsets (thread-constant). No 64-bit address math in the mainloop.
// 4 warps in 2(M) x 2(N) grid; warp tile 32x64.
// Smem: K-major 128B rows, SW128 swizzle -> conflict-free ldmatrix.
// ---------------------------------------------------------------------------
__global__ void __launch_bounds__(NTHREADS, 4)
gemm_f16_kernel(const float* __restrict__ bias, float* __restrict__ out) {
    extern __shared__ __align__(1024) char smem[];
    const uint32_t sbase = smem_u32(smem);
    const int tid  = threadIdx.x;
    const int wid  = tid >> 5;
    const int lane = tid & 31;
    const int wm   = wid & 1;        // warp M coord (2)
    const int wn   = wid >> 1;       // warp N coord (2)

    // M-fastest CTA order: concurrent CTAs share B bands; A stays L2-resident.
    const int mt = blockIdx.x & (NMT - 1);  // 64 M tiles
    const int nt = blockIdx.x >> 6;         // 86 N tiles
    const int m0 = mt * BM;
    const int n0 = nt * BN;

    // Per-thread load geometry: 16B chunk lc of row (lr + j*16).
    const int lr = tid >> 3;          // base row 0..15
    const int lc = tid & 7;           // 16B chunk 0..7

    // Loop-carried global pointers (advance += BK per k-iteration); the row
    // offsets j*16*IN_F are compile-time immediates off these.
    const __half* aCur = g_Xh + (size_t)(m0 + lr) * IN_F + lc * 8;
    const __half* bCur = g_Bh + (size_t)(n0 + lr) * IN_F + lc * 8;

    // Thread-constant swizzled smem store offsets.
    uint32_t swA[4], swB[8];
    #pragma unroll
    for (int j = 0; j < 4; j++) {
        uint32_t off = (uint32_t)((lr + j * 16) * 128 + lc * 16);
        swA[j] = off ^ ((off >> 3) & 0x70);
    }
    #pragma unroll
    for (int j = 0; j < 8; j++) {
        uint32_t off = (uint32_t)((lr + j * 16) * 128 + lc * 16);
        swB[j] = off ^ ((off >> 3) & 0x70);
    }

    // Load one stage into buffer at stage_base from the current pointers.
    auto load_stage = [&](uint32_t stage_base) {
        #pragma unroll
        for (int j = 0; j < 4; j++)
            asm volatile("cp.async.cg.shared.global [%0], [%1], 16;"
                         :: "r"(stage_base + swA[j]),
                            "l"(aCur + (size_t)j * 16 * IN_F) : "memory");
        #pragma unroll
        for (int j = 0; j < 8; j++)
            asm volatile("cp.async.cg.shared.global [%0], [%1], 16;"
                         :: "r"(stage_base + A_STAGE_BYTES + swB[j]),
                            "l"(bCur + (size_t)j * 16 * IN_F) : "memory");
    };

    // Prologue: fill stage 0 (k-iteration 0), then advance pointers.
    load_stage(sbase);
    asm volatile("cp.async.commit_group;" ::: "memory");
    aCur += BK;
    bCur += BK;

    float acc[2][8][4];
    #pragma unroll
    for (int mi = 0; mi < 2; mi++)
        #pragma unroll
        for (int nf = 0; nf < 8; nf++)
            #pragma unroll
            for (int e = 0; e < 4; e++) acc[mi][nf][e] = 0.0f;

    const int lrow   = lane & 15;    // ldmatrix source row within 16
    const int lchunk = lane >> 4;    // 0: k0-7 chunk, 1: k8-15 chunk

    for (int kt = 0; kt < NKIT; kt++) {
        asm volatile("cp.async.wait_group %0;" :: "n"(0) : "memory");
        __syncthreads();

        // Prefetch stage kt+1 (its buffer was consumed at kt-1; all warps
        // passed the barrier above, so it is free). Lands during compute(kt).
        if (kt + 1 < NKIT) {
            load_stage(sbase + ((kt + 1) & 1) * STAGE_BYTES);
            aCur += BK;
            bCur += BK;
        }
        asm volatile("cp.async.commit_group;" ::: "memory");

        // Compute on stage s.
        const uint32_t abuf = sbase + (kt & 1) * STAGE_BYTES;
        const uint32_t bbuf = abuf + A_STAGE_BYTES;

        #pragma unroll
        for (int k16 = 0; k16 < BK / 16; k16++) {
            uint32_t af[2][4], bf[4][4];
            const int chunk = k16 * 2 + lchunk;
            #pragma unroll
            for (int mi = 0; mi < 2; mi++) {
                int row = wm * 32 + mi * 16 + lrow;
                uint32_t off = (uint32_t)(row * 128 + chunk * 16);
                ldsm_x4(abuf + (off ^ ((off >> 3) & 0x70)), af[mi]);
            }
            #pragma unroll
            for (int nj = 0; nj < 4; nj++) {
                int row = wn * 64 + nj * 16 + lrow;
                uint32_t off = (uint32_t)(row * 128 + chunk * 16);
                ldsm_x4(bbuf + (off ^ ((off >> 3) & 0x70)), bf[nj]);
            }
            #pragma unroll
            for (int mi = 0; mi < 2; mi++)
                #pragma unroll
                for (int nj = 0; nj < 4; nj++) {
                    mma16816(acc[mi][2 * nj],     af[mi], bf[nj][0], bf[nj][2]);
                    mma16816(acc[mi][2 * nj + 1], af[mi], bf[nj][1], bf[nj][3]);
                }
        }
    }

    // Epilogue: fragment layout c0,c1 -> (row=q, col=2c..2c+1), c2,c3 -> row+8.
    const int qrow = lane >> 2;          // 0..7
    const int qcol = (lane & 3) * 2;
    #pragma unroll
    for (int mi = 0; mi < 2; mi++) {
        int gr = m0 + wm * 32 + mi * 16 + qrow;
        float* p0 = out + (size_t)gr * OUT_F;
        float* p1 = p0 + 8 * OUT_F;
        #pragma unroll
        for (int nf = 0; nf < 8; nf++) {
            int col = n0 + wn * 64 + nf * 8 + qcol;
            float bx = __ldg(bias + col);
            float by = __ldg(bias + col + 1);
            float2 v0, v1;
            v0.x = acc[mi][nf][0] + bx;
            v0.y = acc[mi][nf][1] + by;
            v1.x = acc[mi][nf][2] + bx;
            v1.y = acc[mi][nf][3] + by;
            *reinterpret_cast<float2*>(p0 + col) = v0;
            *reinterpret_cast<float2*>(p1 + col) = v1;
        }
    }
}

// ---------------------------------------------------------------------------
extern "C" void kernel_launch(void* const* d_in, const int* in_sizes, int n_in,
                              void* d_out, int out_size) {
    const float*    x    = (const float*)   d_in[0];
    const uint32_t* qw   = (const uint32_t*)d_in[1];
    const uint32_t* qz   = (const uint32_t*)d_in[2];
    const float*    sc   = (const float*)   d_in[3];
    const float*    bias = (const float*)   d_in[4];
    float*          out  = (float*)d_out;

    // 1) fused: x -> fp16  ||  int4 dequant -> fp16 (concurrent)
    prep_kernel<<<NCONV_BLKS + NDEQ_BLKS, 256>>>((const float4*)x, qw, qz, sc);

    // 2) fp16 mma.sync GEMM, 4 CTAs/SM, strength-reduced addressing
    cudaFuncSetAttribute(gemm_f16_kernel,
                         cudaFuncAttributeMaxDynamicSharedMemorySize, SMEM_TOTAL);
    dim3 grid(NMT * NNT);  // 64 * 86 = 5504, M-fastest
    gemm_f16_kernel<<<grid, NTHREADS, SMEM_TOTAL>>>(bias, out);
}

// round 16
// speedup vs baseline: 1.0902x; 1.0034x over previous
#include <cuda_runtime.h>
#include <cuda_fp16.h>
#include <cstdint>

// Problem constants
#define TOKENS   4096
#define IN_F     4096
#define OUT_F    11008
#define QGROUPS  64
#define KWORDS   (IN_F / 8)       // 512 packed int32 per output row

// GEMM tiling: 64x128x64, 2-stage, 4 CTAs/SM (16 warps/SM). R13/R15 mainloop.
#define BM       64
#define BN       128
#define BK       64               // fp16 elements per stage along K (128B rows)
#define NKIT     (IN_F / BK)      // 64
#define NTHREADS 128              // 4 warps, 2x2 grid of 32x64 warp tiles
#define A_STAGE_BYTES (BM * BK * 2)               // 8192
#define B_STAGE_BYTES (BN * BK * 2)               // 16384
#define STAGE_BYTES   (A_STAGE_BYTES + B_STAGE_BYTES)  // 24576
#define SMEM_TOTAL    (2 * STAGE_BYTES)           // 49152 (4 CTAs -> 192KB/SM)

#define NMT      (TOKENS / BM)    // 64 M tiles
#define NNT      (OUT_F / BN)     // 86 N tiles
#define NTILES   (NMT * NNT)      // 5504
#define NSLOTS   592              // 148 SMs * 4 CTAs
#define NFULL    (NSLOTS * 9)     // 5328 full tiles = exactly 9 waves
#define NSPLIT   (NTILES - NFULL) // 176 remainder tiles, each split into 2 K-halves
#define GRID_GEMM (NFULL + 2 * NSPLIT)  // 5680

// Scratch (device globals: allocation-free rule)
__device__ __half g_Bh[(size_t)OUT_F * IN_F];   // dequantized fp16 weights
__device__ __half g_Xh[(size_t)TOKENS * IN_F];  // fp16 activations

// ---------------------------------------------------------------------------
// Helpers
// ---------------------------------------------------------------------------
__device__ __forceinline__ uint32_t smem_u32(const void* p) {
    uint32_t a;
    asm("{ .reg .u64 t; cvta.to.shared.u64 t, %1; cvt.u32.u64 %0, t; }"
        : "=r"(a) : "l"(p));
    return a;
}

__device__ __forceinline__ void ldsm_x4(uint32_t addr, uint32_t* r) {
    asm volatile("ldmatrix.sync.aligned.m8n8.x4.shared.b16 {%0,%1,%2,%3}, [%4];"
                 : "=r"(r[0]), "=r"(r[1]), "=r"(r[2]), "=r"(r[3]) : "r"(addr));
}

__device__ __forceinline__ void mma16816(float* c, const uint32_t* a,
                                         uint32_t b0, uint32_t b1) {
    asm volatile(
        "mma.sync.aligned.m16n8k16.row.col.f32.f16.f16.f32 "
        "{%0,%1,%2,%3}, {%4,%5,%6,%7}, {%8,%9}, {%0,%1,%2,%3};"
        : "+f"(c[0]), "+f"(c[1]), "+f"(c[2]), "+f"(c[3])
        : "r"(a[0]), "r"(a[1]), "r"(a[2]), "r"(a[3]), "r"(b0), "r"(b1));
}

__device__ __forceinline__ void red_add_f32(float* p, float v) {
    asm volatile("red.global.add.f32 [%0], %1;" :: "l"(p), "f"(v) : "memory");
}

// ---------------------------------------------------------------------------
// Fused pre-kernel, three segments:
//  [0, NCONV_BLKS)                 : x -> fp16
//  [NCONV_BLKS, +NDEQ_BLKS)        : int4 dequant -> fp16
//  [.., +NINIT_BLKS)               : init out regions of the 176 split tiles
//                                    with bias (so both K-halves can red.add
//                                    race-free, order-commutatively).
// ---------------------------------------------------------------------------
#define NCONV_ELEMS (TOKENS * IN_F / 8)           // uint4 stores: 2097152
#define NCONV_BLKS  ((NCONV_ELEMS + 255) / 256)   // 8192
#define NDEQ_ELEMS  (OUT_F * KWORDS)              // 5636096
#define NDEQ_BLKS   ((NDEQ_ELEMS + 255) / 256)    // 22016
#define NINIT_BLKS  (NSPLIT * 8)                  // 176 tiles * 2048 float4 / 256

__global__ void prep_kernel(const float4* __restrict__ x,
                            const uint32_t* __restrict__ qw,
                            const uint32_t* __restrict__ qz,
                            const float* __restrict__ sc,
                            const float* __restrict__ bias,
                            float* __restrict__ out) {
    if (blockIdx.x < NCONV_BLKS) {
        int i = blockIdx.x * 256 + threadIdx.x;
        if (i >= NCONV_ELEMS) return;
        float4 a = x[2 * i];
        float4 b = x[2 * i + 1];
        __half2 h0 = __floats2half2_rn(a.x, a.y);
        __half2 h1 = __floats2half2_rn(a.z, a.w);
        __half2 h2 = __floats2half2_rn(b.x, b.y);
        __half2 h3 = __floats2half2_rn(b.z, b.w);
        uint4 o;
        o.x = *reinterpret_cast<uint32_t*>(&h0);
        o.y = *reinterpret_cast<uint32_t*>(&h1);
        o.z = *reinterpret_cast<uint32_t*>(&h2);
        o.w = *reinterpret_cast<uint32_t*>(&h3);
        reinterpret_cast<uint4*>(g_Xh)[i] = o;
    } else if (blockIdx.x < NCONV_BLKS + NDEQ_BLKS) {
        int idx = (blockIdx.x - NCONV_BLKS) * 256 + threadIdx.x;
        if (idx >= NDEQ_ELEMS) return;
        int o  = idx >> 9;              // / 512
        int kw = idx & (KWORDS - 1);
        int g  = kw >> 3;               // group (8 words per 64-elem group)
        float s = sc[o * QGROUPS + g];
        uint32_t zw = qz[o * (QGROUPS / 8) + (g >> 3)];
        float zp = (float)((zw >> ((g & 7) * 4)) & 0xF);
        float c  = -s * zp;             // w = s*v + c; |w| <= 0.15, fp16-safe
        uint32_t w = qw[idx];
        __half2 h0 = __floats2half2_rn(fmaf(s, (float)((w      ) & 0xF), c),
                                       fmaf(s, (float)((w >>  4) & 0xF), c));
        __half2 h1 = __floats2half2_rn(fmaf(s, (float)((w >>  8) & 0xF), c),
                                       fmaf(s, (float)((w >> 12) & 0xF), c));
        __half2 h2 = __floats2half2_rn(fmaf(s, (float)((w >> 16) & 0xF), c),
                                       fmaf(s, (float)((w >> 20) & 0xF), c));
        __half2 h3 = __floats2half2_rn(fmaf(s, (float)((w >> 24) & 0xF), c),
                                       fmaf(s, (float)((w >> 28) & 0xF), c));
        uint4 o4;
        o4.x = *reinterpret_cast<uint32_t*>(&h0);
        o4.y = *reinterpret_cast<uint32_t*>(&h1);
        o4.z = *reinterpret_cast<uint32_t*>(&h2);
        o4.w = *reinterpret_cast<uint32_t*>(&h3);
        reinterpret_cast<uint4*>(g_Bh + (size_t)o * IN_F)[kw] = o4;
    } else {
        // Init split-tile out regions with bias (8 blocks per tile).
        int j = blockIdx.x - NCONV_BLKS - NDEQ_BLKS;       // 0..NINIT_BLKS-1
        int t = j >> 3;                                    // split tile 0..175
        int inner = (j & 7) * 256 + threadIdx.x;           // 0..2047
        int row = inner >> 5;                              // 0..63
        int c4  = inner & 31;                              // float4 col 0..31
        int tile = NFULL + t;
        int m0 = (tile & (NMT - 1)) * BM;
        int n0 = (tile >> 6) * BN;
        float4 bv = *reinterpret_cast<const float4*>(bias + n0 + c4 * 4);
        *reinterpret_cast<float4*>(out + (size_t)(m0 + row) * OUT_F
                                   + n0 + c4 * 4) = bv;
    }
}

// ---------------------------------------------------------------------------
// Main GEMM: mma.sync.m16n8k16 fp16 -> f32, CTA 64x128x64, 2-stage cp.async,
// 4 CTAs per SM (16 warps/SM). Blocks [0, NFULL) are full-K tiles (exactly 9
// perfect waves of 592). Blocks [NFULL, NFULL+352) are the 176 remainder
// tiles split into 2 K-halves (32 kt each): they red.add into out, which the
// prep kernel pre-initialized with bias -> order-free across the two halves.
// Smem: K-major 128B rows, SW128 swizzle -> conflict-free ldmatrix.
// ---------------------------------------------------------------------------
__global__ void __launch_bounds__(NTHREADS, 4)
gemm_f16_kernel(const float* __restrict__ bias, float* __restrict__ out) {
    extern __shared__ __align__(1024) char smem[];
    const uint32_t sbase = smem_u32(smem);
    const int tid  = threadIdx.x;
    const int wid  = tid >> 5;
    const int lane = tid & 31;
    const int wm   = wid & 1;        // warp M coord (2)
    const int wn   = wid >> 1;       // warp N coord (2)

    // Tile / K-range decode.
    int tile, k0e, nk;
    bool split;
    if (blockIdx.x < NFULL) {
        tile = blockIdx.x;  k0e = 0;  nk = NKIT;  split = false;
    } else {
        int sp   = blockIdx.x - NFULL;           // 0..351
        int half = (sp >= NSPLIT) ? 1 : 0;
        tile  = NFULL + (sp - half * NSPLIT);    // 5328..5503
        k0e   = half * (IN_F / 2);               // element offset into K
        nk    = NKIT / 2;                        // 32 k-iterations
        split = true;
    }
    const int m0 = (tile & (NMT - 1)) * BM;
    const int n0 = (tile >> 6) * BN;

    // Per-thread load geometry: 16B chunk lc of row (lr + j*16).
    const int lr = tid >> 3;          // base row 0..15
    const int lc = tid & 7;           // 16B chunk 0..7

    const __half* aCur = g_Xh + (size_t)(m0 + lr) * IN_F + lc * 8 + k0e;
    const __half* bCur = g_Bh + (size_t)(n0 + lr) * IN_F + lc * 8 + k0e;

    // Thread-constant swizzled smem store offsets.
    uint32_t swA[4], swB[8];
    #pragma unroll
    for (int j = 0; j < 4; j++) {
        uint32_t off = (uint32_t)((lr + j * 16) * 128 + lc * 16);
        swA[j] = off ^ ((off >> 3) & 0x70);
    }
    #pragma unroll
    for (int j = 0; j < 8; j++) {
        uint32_t off = (uint32_t)((lr + j * 16) * 128 + lc * 16);
        swB[j] = off ^ ((off >> 3) & 0x70);
    }

    auto load_stage = [&](uint32_t stage_base) {
        #pragma unroll
        for (int j = 0; j < 4; j++)
            asm volatile("cp.async.cg.shared.global [%0], [%1], 16;"
                         :: "r"(stage_base + swA[j]),
                            "l"(aCur + (size_t)j * 16 * IN_F) : "memory");
        #pragma unroll
        for (int j = 0; j < 8; j++)
            asm volatile("cp.async.cg.shared.global [%0], [%1], 16;"
                         :: "r"(stage_base + A_STAGE_BYTES + swB[j]),
                            "l"(bCur + (size_t)j * 16 * IN_F) : "memory");
    };

    // Prologue: fill stage 0, advance pointers.
    load_stage(sbase);
    asm volatile("cp.async.commit_group;" ::: "memory");
    aCur += BK;
    bCur += BK;

    float acc[2][8][4];
    #pragma unroll
    for (int mi = 0; mi < 2; mi++)
        #pragma unroll
        for (int nf = 0; nf < 8; nf++)
            #pragma unroll
            for (int e = 0; e < 4; e++) acc[mi][nf][e] = 0.0f;

    const int lrow   = lane & 15;    // ldmatrix source row within 16
    const int lchunk = lane >> 4;    // 0: k0-7 chunk, 1: k8-15 chunk

    for (int kt = 0; kt < nk; kt++) {
        asm volatile("cp.async.wait_group %0;" :: "n"(0) : "memory");
        __syncthreads();

        if (kt + 1 < nk) {
            load_stage(sbase + ((kt + 1) & 1) * STAGE_BYTES);
            aCur += BK;
            bCur += BK;
        }
        asm volatile("cp.async.commit_group;" ::: "memory");

        const uint32_t abuf = sbase + (kt & 1) * STAGE_BYTES;
        const uint32_t bbuf = abuf + A_STAGE_BYTES;

        #pragma unroll
        for (int k16 = 0; k16 < BK / 16; k16++) {
            uint32_t af[2][4], bf[4][4];
            const int chunk = k16 * 2 + lchunk;
            #pragma unroll
            for (int mi = 0; mi < 2; mi++) {
                int row = wm * 32 + mi * 16 + lrow;
                uint32_t off = (uint32_t)(row * 128 + chunk * 16);
                ldsm_x4(abuf + (off ^ ((off >> 3) & 0x70)), af[mi]);
            }
            #pragma unroll
            for (int nj = 0; nj < 4; nj++) {
                int row = wn * 64 + nj * 16 + lrow;
                uint32_t off = (uint32_t)(row * 128 + chunk * 16);
                ldsm_x4(bbuf + (off ^ ((off >> 3) & 0x70)), bf[nj]);
            }
            #pragma unroll
            for (int mi = 0; mi < 2; mi++)
                #pragma unroll
                for (int nj = 0; nj < 4; nj++) {
                    mma16816(acc[mi][2 * nj],     af[mi], bf[nj][0], bf[nj][2]);
                    mma16816(acc[mi][2 * nj + 1], af[mi], bf[nj][1], bf[nj][3]);
                }
        }
    }

    // Epilogue. Full tiles: store acc+bias. Split tiles: red.add partial sums
    // into pre-initialized (bias) out -- commutative across the two halves.
    const int qrow = lane >> 2;          // 0..7
    const int qcol = (lane & 3) * 2;
    #pragma unroll
    for (int mi = 0; mi < 2; mi++) {
        int gr = m0 + wm * 32 + mi * 16 + qrow;
        float* p0 = out + (size_t)gr * OUT_F;
        float* p1 = p0 + 8 * OUT_F;
        #pragma unroll
        for (int nf = 0; nf < 8; nf++) {
            int col = n0 + wn * 64 + nf * 8 + qcol;
            if (!split) {
                float bx = __ldg(bias + col);
                float by = __ldg(bias + col + 1);
                float2 v0, v1;
                v0.x = acc[mi][nf][0] + bx;
                v0.y = acc[mi][nf][1] + by;
                v1.x = acc[mi][nf][2] + bx;
                v1.y = acc[mi][nf][3] + by;
                *reinterpret_cast<float2*>(p0 + col) = v0;
                *reinterpret_cast<float2*>(p1 + col) = v1;
            } else {
                red_add_f32(p0 + col,     acc[mi][nf][0]);
                red_add_f32(p0 + col + 1, acc[mi][nf][1]);
                red_add_f32(p1 + col,     acc[mi][nf][2]);
                red_add_f32(p1 + col + 1, acc[mi][nf][3]);
            }
        }
    }
}

// ---------------------------------------------------------------------------
extern "C" void kernel_launch(void* const* d_in, const int* in_sizes, int n_in,
                              void* d_out, int out_size) {
    const float*    x    = (const float*)   d_in[0];
    const uint32_t* qw   = (const uint32_t*)d_in[1];
    const uint32_t* qz   = (const uint32_t*)d_in[2];
    const float*    sc   = (const float*)   d_in[3];
    const float*    bias = (const float*)   d_in[4];
    float*          out  = (float*)d_out;

    // 1) fused prep: x->fp16 || dequant->fp16 || bias-init of split regions
    prep_kernel<<<NCONV_BLKS + NDEQ_BLKS + NINIT_BLKS, 256>>>(
        (const float4*)x, qw, qz, sc, bias, out);

    // 2) fp16 mma.sync GEMM: 9 perfect waves of full tiles + split-K tail
    cudaFuncSetAttribute(gemm_f16_kernel,
                         cudaFuncAttributeMaxDynamicSharedMemorySize, SMEM_TOTAL);
    gemm_f16_kernel<<<GRID_GEMM, NTHREADS, SMEM_TOTAL>>>(bias, out);
}